// round 1
// baseline (speedup 1.0000x reference)
#include <cuda_runtime.h>
#include <cuda_bf16.h>
#include <math.h>

// Problem constants (fixed by the reference setup)
#define B   128
#define V   4
#define D   128
#define N   512      // B*V
#define EPSN 1e-12f

// Scratch (device globals — no allocation allowed)
__device__ float              g_emb[N * D];      // normalized embeddings, view-major
__device__ float              g_sqn[N];          // per-row squared norms (post-normalize)
__device__ float              g_dist[N * N];     // pairwise euclidean distances
__device__ double             g_sum;             // triplet loss accumulator
__device__ unsigned long long g_cnt;             // nonzero-loss count

// ---------------------------------------------------------------------------
// Kernel 1: restack (view-major), L2-normalize, compute sq_norm.
// grid = N blocks, 128 threads (one per feature dim).
// emb[n = v*B + b, d] = features[b, v, d]
// ---------------------------------------------------------------------------
__global__ void normalize_kernel(const float* __restrict__ feat) {
    int n = blockIdx.x;          // 0..511
    int d = threadIdx.x;         // 0..127
    if (n == 0 && d == 0) { g_sum = 0.0; g_cnt = 0ULL; }   // reset accumulators each replay

    int b = n & (B - 1);
    int v = n >> 7;              // n / B
    float x = feat[b * (V * D) + v * D + d];

    // block reduce sum(x*x) over 128 threads (4 warps)
    __shared__ float red[4];
    float s = x * x;
    #pragma unroll
    for (int o = 16; o > 0; o >>= 1) s += __shfl_down_sync(0xffffffffu, s, o);
    if ((d & 31) == 0) red[d >> 5] = s;
    __syncthreads();
    float tot = red[0] + red[1] + red[2] + red[3];

    float inv = 1.0f / fmaxf(sqrtf(tot), EPSN);
    float e = x * inv;
    g_emb[n * D + d] = e;

    // explicit sq_norm of the normalized row (matches reference exactly)
    __shared__ float red2[4];
    float s2 = e * e;
    #pragma unroll
    for (int o = 16; o > 0; o >>= 1) s2 += __shfl_down_sync(0xffffffffu, s2, o);
    if ((d & 31) == 0) red2[d >> 5] = s2;
    __syncthreads();
    if (d == 0) g_sqn[n] = red2[0] + red2[1] + red2[2] + red2[3];
}

// ---------------------------------------------------------------------------
// Kernel 2: pairwise distance matrix.
// grid = N blocks (one per row i), 512 threads (one per column j).
// d[i,j] = sq>0 ? sqrt(sq) : 0,  sq = sqn_i + sqn_j - 2*dot(emb_i, emb_j)
// ---------------------------------------------------------------------------
__global__ void dist_kernel() {
    int i = blockIdx.x;
    int j = threadIdx.x;         // 0..511

    __shared__ float4 si[D / 4];
    if (j < D / 4) si[j] = reinterpret_cast<const float4*>(g_emb + i * D)[j];
    __syncthreads();

    const float4* rj = reinterpret_cast<const float4*>(g_emb + j * D);
    float dot = 0.0f;
    #pragma unroll
    for (int k = 0; k < D / 4; k++) {
        float4 a = si[k];
        float4 bb = rj[k];
        dot += a.x * bb.x + a.y * bb.y + a.z * bb.z + a.w * bb.w;
    }
    float sq = g_sqn[i] + g_sqn[j] - 2.0f * dot;
    g_dist[i * N + j] = (sq > 0.0f) ? sqrtf(sq) : 0.0f;
}

// ---------------------------------------------------------------------------
// Kernel 3: triplet reduction.
// grid = N blocks (one per anchor a), 256 threads.
// For each valid positive p (same label, p != a) and negative n (diff label):
//   diff = d[a,p] - d[a,n]; if diff > 0: sum += diff, cnt++
// ---------------------------------------------------------------------------
__global__ void triplet_kernel(const int* __restrict__ labels) {
    int a = blockIdx.x;
    int t = threadIdx.x;         // 0..255

    __shared__ float sd[N];
    __shared__ int   slab[N];
    __shared__ int   spos[N];
    __shared__ int   npos;
    __shared__ float        ssum[8];
    __shared__ unsigned int scnt[8];

    if (t == 0) npos = 0;
    sd[t]        = g_dist[a * N + t];
    sd[t + 256]  = g_dist[a * N + t + 256];
    slab[t]       = labels[t & (B - 1)];          // tiled labels: lab[n] = labels[n % B]
    slab[t + 256] = labels[(t + 256) & (B - 1)];
    __syncthreads();

    int la = slab[a];

    // gather positive indices
    for (int p = t; p < N; p += 256) {
        if (slab[p] == la && p != a) {
            int idx = atomicAdd(&npos, 1);
            spos[idx] = p;
        }
    }
    __syncthreads();
    int P = npos;

    float        lsum = 0.0f;
    unsigned int lcnt = 0;
    for (int n = t; n < N; n += 256) {
        if (slab[n] != la) {
            float dan = sd[n];
            for (int q = 0; q < P; q++) {
                float diff = sd[spos[q]] - dan;   // margin = 0
                if (diff > 0.0f) { lsum += diff; lcnt++; }
            }
        }
    }

    // block reduce
    #pragma unroll
    for (int o = 16; o > 0; o >>= 1) {
        lsum += __shfl_down_sync(0xffffffffu, lsum, o);
        lcnt += __shfl_down_sync(0xffffffffu, lcnt, o);
    }
    if ((t & 31) == 0) { ssum[t >> 5] = lsum; scnt[t >> 5] = lcnt; }
    __syncthreads();
    if (t == 0) {
        float bs = 0.0f; unsigned int bc = 0;
        #pragma unroll
        for (int w = 0; w < 8; w++) { bs += ssum[w]; bc += scnt[w]; }
        atomicAdd(&g_sum, (double)bs);
        atomicAdd(&g_cnt, (unsigned long long)bc);
    }
}

// ---------------------------------------------------------------------------
// Kernel 4: finalize — mean over nonzero losses (AvgNonZeroReducer)
// ---------------------------------------------------------------------------
__global__ void finalize_kernel(float* __restrict__ out) {
    out[0] = (g_cnt > 0ULL) ? (float)(g_sum / (double)g_cnt) : 0.0f;
}

extern "C" void kernel_launch(void* const* d_in, const int* in_sizes, int n_in,
                              void* d_out, int out_size) {
    const float* feat   = (const float*)d_in[0];   // [128, 4, 128] float32
    const int*   labels = (const int*)d_in[1];     // [128] int32
    float*       out    = (float*)d_out;           // scalar float32

    normalize_kernel<<<N, D>>>(feat);
    dist_kernel<<<N, N>>>();
    triplet_kernel<<<N, 256>>>(labels);
    finalize_kernel<<<1, 1>>>(out);
}

// round 2
// speedup vs baseline: 1.7869x; 1.7869x over previous
#include <cuda_runtime.h>
#include <math.h>

// Problem constants (fixed by the reference setup)
#define Bd   128
#define Vd   4
#define Dd   128
#define Nd   512          // B*V
#define ANCH 4            // anchors per block
#define GRID (Nd / ANCH)  // 128 blocks = one wave on 148 SMs
#define NT   512          // threads per block (16 warps)

// Scratch (device globals — no allocation allowed)
__device__ float        g_part[GRID];
__device__ unsigned int g_cntp[GRID];
__device__ unsigned int g_done = 0;

// 5-value warp butterfly reduction
#define BFLY5(a, b, c, d, e)                                  \
    _Pragma("unroll")                                         \
    for (int _o = 16; _o > 0; _o >>= 1) {                     \
        a += __shfl_xor_sync(0xffffffffu, a, _o);             \
        b += __shfl_xor_sync(0xffffffffu, b, _o);             \
        c += __shfl_xor_sync(0xffffffffu, c, _o);             \
        d += __shfl_xor_sync(0xffffffffu, d, _o);             \
        e += __shfl_xor_sync(0xffffffffu, e, _o);             \
    }

__global__ void __launch_bounds__(NT, 1)
fused_triplet_kernel(const float* __restrict__ feat,
                     const int*   __restrict__ labels,
                     float*       __restrict__ out) {
    const int t    = threadIdx.x;
    const int w    = t >> 5;
    const int lane = t & 31;
    const int blk  = blockIdx.x;

    __shared__ float        sd[ANCH][Nd];   // distance rows for the 4 anchors (8 KB)
    __shared__ int          slab[Nd];       // tiled labels (2 KB)
    __shared__ int          spos[Nd];       // positive indices for current anchor
    __shared__ int          snpos;
    __shared__ float        swsum[16];
    __shared__ unsigned int swcnt[16];
    __shared__ int          sIsLast;

    // labels: lab[n] = labels[n % 128]
    slab[t] = labels[t & (Bd - 1)];

    // ---- load the 4 anchor rows into registers, compute 1/||a|| ----
    // emb row n <- features[n & 127, n >> 7, :]  (view-major restack)
    float4 areg[ANCH];
    float  inv_na[ANCH];
#pragma unroll
    for (int i = 0; i < ANCH; i++) {
        int n = blk * ANCH + i;
        const float4* p = reinterpret_cast<const float4*>(
            feat + (size_t)(n & (Bd - 1)) * (Vd * Dd) + (n >> 7) * Dd);
        float4 a = p[lane];
        areg[i] = a;
        float s = a.x * a.x + a.y * a.y + a.z * a.z + a.w * a.w;
#pragma unroll
        for (int o = 16; o > 0; o >>= 1) s += __shfl_xor_sync(0xffffffffu, s, o);
        inv_na[i] = 1.0f / sqrtf(s);
    }

    // ---- distance rows: warp w handles rows j = w*32 .. w*32+31 ----
    for (int jj = 0; jj < 32; jj++) {
        int j = (w << 5) + jj;
        const float4* p = reinterpret_cast<const float4*>(
            feat + (size_t)(j & (Bd - 1)) * (Vd * Dd) + (j >> 7) * Dd);
        float4 f = p[lane];   // coalesced: 32 lanes = contiguous 512B row

        float sq = f.x * f.x + f.y * f.y + f.z * f.z + f.w * f.w;
        float p0 = f.x * areg[0].x + f.y * areg[0].y + f.z * areg[0].z + f.w * areg[0].w;
        float p1 = f.x * areg[1].x + f.y * areg[1].y + f.z * areg[1].z + f.w * areg[1].w;
        float p2 = f.x * areg[2].x + f.y * areg[2].y + f.z * areg[2].z + f.w * areg[2].w;
        float p3 = f.x * areg[3].x + f.y * areg[3].y + f.z * areg[3].z + f.w * areg[3].w;

        BFLY5(sq, p0, p1, p2, p3);

        if (lane < 4) {
            float inv_nj = 1.0f / sqrtf(sq);
            float pv  = (lane == 0) ? p0 : (lane == 1) ? p1 : (lane == 2) ? p2 : p3;
            float ina = (lane == 0) ? inv_na[0] : (lane == 1) ? inv_na[1]
                      : (lane == 2) ? inv_na[2] : inv_na[3];
            float c   = pv * ina * inv_nj;
            float sqd = 2.0f - 2.0f * c;
            sd[lane][j] = (sqd > 0.0f) ? sqrtf(sqd) : 0.0f;
        }
    }
    __syncthreads();

    // ---- triplet reduction over the 4 anchor rows ----
    float        lsum = 0.0f;
    unsigned int lcnt = 0;

#pragma unroll
    for (int i = 0; i < ANCH; i++) {
        int a  = blk * ANCH + i;
        int la = slab[a];

        if (t == 0) snpos = 0;
        __syncthreads();
        if (slab[t] == la && t != a) {
            int k = atomicAdd(&snpos, 1);
            spos[k] = t;
        }
        __syncthreads();
        int P = snpos;

        // thread t is candidate negative n = t
        if (slab[t] != la) {
            float dan = sd[i][t];
            for (int q = 0; q < P; q++) {
                float diff = sd[i][spos[q]] - dan;   // margin = 0
                if (diff > 0.0f) { lsum += diff; lcnt++; }
            }
        }
        __syncthreads();   // protect spos/snpos before next anchor
    }

    // ---- block reduce (sum, count) ----
#pragma unroll
    for (int o = 16; o > 0; o >>= 1) {
        lsum += __shfl_xor_sync(0xffffffffu, lsum, o);
        lcnt += __shfl_xor_sync(0xffffffffu, lcnt, o);
    }
    if (lane == 0) { swsum[w] = lsum; swcnt[w] = lcnt; }
    __syncthreads();

    if (t == 0) {
        float bs = 0.0f; unsigned int bc = 0;
#pragma unroll
        for (int k = 0; k < 16; k++) { bs += swsum[k]; bc += swcnt[k]; }
        g_part[blk] = bs;
        g_cntp[blk] = bc;
        __threadfence();
        unsigned int old = atomicAdd(&g_done, 1);
        sIsLast = (old == GRID - 1);
    }
    __syncthreads();

    // ---- last block finalizes (AvgNonZeroReducer) ----
    if (sIsLast) {
        __threadfence();
        float        s = 0.0f;
        unsigned int c = 0;
        if (t < GRID) {
            s = ((volatile float*)g_part)[t];
            c = ((volatile unsigned int*)g_cntp)[t];
        }
#pragma unroll
        for (int o = 16; o > 0; o >>= 1) {
            s += __shfl_xor_sync(0xffffffffu, s, o);
            c += __shfl_xor_sync(0xffffffffu, c, o);
        }
        if (t < GRID && lane == 0) { swsum[w] = s; swcnt[w] = c; }
        __syncthreads();
        if (t == 0) {
            float S = swsum[0] + swsum[1] + swsum[2] + swsum[3];
            unsigned int C = swcnt[0] + swcnt[1] + swcnt[2] + swcnt[3];
            out[0] = (C > 0) ? (S / (float)C) : 0.0f;
            g_done = 0;   // reset for next graph replay
        }
    }
}

extern "C" void kernel_launch(void* const* d_in, const int* in_sizes, int n_in,
                              void* d_out, int out_size) {
    const float* feat   = (const float*)d_in[0];   // [128, 4, 128] float32
    const int*   labels = (const int*)d_in[1];     // [128] int32
    float*       out    = (float*)d_out;           // scalar float32

    fused_triplet_kernel<<<GRID, NT>>>(feat, labels, out);
}

// round 3
// speedup vs baseline: 3.3093x; 1.8520x over previous
#include <cuda_runtime.h>
#include <math.h>

// Problem constants (fixed by the reference setup)
#define Bd   128
#define Vd   4
#define Dd   128
#define Nd   512           // B*V
#define ANCH 4             // anchors per block
#define GRID (Nd / ANCH)   // 128 blocks
#define NT   512           // threads per block (16 warps)
#define TILE 256           // rows staged per tile
#define RS   132           // padded row stride in floats (conflict-free LDS.128)

#define DYN_SMEM_FLOATS (TILE*RS + ANCH*Nd + ANCH*Dd + TILE*5)
#define DYN_SMEM_BYTES  (DYN_SMEM_FLOATS * 4)

// Scratch (device globals — no allocation allowed)
__device__ float        g_part[GRID];
__device__ unsigned int g_cntp[GRID];
__device__ unsigned int g_done = 0;

__global__ void __launch_bounds__(NT, 1)
fused_triplet_kernel(const float* __restrict__ feat,
                     const int*   __restrict__ labels,
                     float*       __restrict__ out) {
    extern __shared__ float smem[];
    float* tile = smem;                  // TILE * RS
    float* sdm  = tile + TILE * RS;      // ANCH * Nd   (distance rows)
    float* sa   = sdm + ANCH * Nd;       // ANCH * Dd   (anchor rows)
    float* prt  = sa + ANCH * Dd;        // TILE * 5    (k-half partials)

    __shared__ int          slab[Nd];
    __shared__ int          spos[Nd];
    __shared__ float        spp[Nd];
    __shared__ int          snpos;
    __shared__ float        s_invna[ANCH];
    __shared__ float        swsum[16];
    __shared__ unsigned int swcnt[16];
    __shared__ int          sIsLast;

    const int t    = threadIdx.x;
    const int w    = t >> 5;
    const int lane = t & 31;
    const int blk  = blockIdx.x;

    // tiled labels: lab[n] = labels[n % 128]
    slab[t] = labels[t & (Bd - 1)];

    // ---- anchors into smem (row n <- features[n & 127, n >> 7, :]) ----
    {
        int i = t >> 7;          // 0..3
        int d = t & (Dd - 1);    // 0..127
        int n = blk * ANCH + i;
        sa[i * Dd + d] = feat[(n & (Bd - 1)) * (Vd * Dd) + (n >> 7) * Dd + d];
    }
    __syncthreads();

    // anchor inverse norms (warps 0..3, one butterfly each)
    if (w < ANCH) {
        float4 v = reinterpret_cast<const float4*>(sa + w * Dd)[lane];
        float s = v.x * v.x + v.y * v.y + v.z * v.z + v.w * v.w;
#pragma unroll
        for (int o = 16; o > 0; o >>= 1) s += __shfl_xor_sync(0xffffffffu, s, o);
        if (lane == 0) s_invna[w] = 1.0f / sqrtf(s);
    }
    // (made visible by the __syncthreads() after tile staging below)

    const int kh = t >> 8;          // k-half: 0 or 1
    const int lr = t & (TILE - 1);  // row within tile

#pragma unroll
    for (int tt = 0; tt < Nd / TILE; tt++) {
        // ---- stage tile: warp w stages rows w*16 .. w*16+15 (coalesced) ----
        {
            int lrow = w * 16;
#pragma unroll
            for (int rr = 0; rr < 16; rr++, lrow++) {
                int r = tt * TILE + lrow;
                const float4* src = reinterpret_cast<const float4*>(
                    feat + (size_t)(r & (Bd - 1)) * (Vd * Dd) + (r >> 7) * Dd);
                reinterpret_cast<float4*>(tile + lrow * RS)[lane] = src[lane];
            }
        }
        __syncthreads();

        // ---- each thread: 4 anchor dots + sq-norm for row lr, k-half kh ----
        float d0 = 0.f, d1 = 0.f, d2 = 0.f, d3 = 0.f, sq = 0.f;
        const float4* rowp = reinterpret_cast<const float4*>(tile + lr * RS + kh * 64);
        const float4* a0p  = reinterpret_cast<const float4*>(sa + 0 * Dd + kh * 64);
        const float4* a1p  = reinterpret_cast<const float4*>(sa + 1 * Dd + kh * 64);
        const float4* a2p  = reinterpret_cast<const float4*>(sa + 2 * Dd + kh * 64);
        const float4* a3p  = reinterpret_cast<const float4*>(sa + 3 * Dd + kh * 64);
#pragma unroll
        for (int c = 0; c < 16; c++) {
            float4 f  = rowp[c];
            float4 a0 = a0p[c];
            float4 a1 = a1p[c];
            float4 a2 = a2p[c];
            float4 a3 = a3p[c];
            sq += f.x * f.x + f.y * f.y + f.z * f.z + f.w * f.w;
            d0 += f.x * a0.x + f.y * a0.y + f.z * a0.z + f.w * a0.w;
            d1 += f.x * a1.x + f.y * a1.y + f.z * a1.z + f.w * a1.w;
            d2 += f.x * a2.x + f.y * a2.y + f.z * a2.z + f.w * a2.w;
            d3 += f.x * a3.x + f.y * a3.y + f.z * a3.z + f.w * a3.w;
        }
        if (kh == 1) {
            float* pp = prt + lr * 5;
            pp[0] = d0; pp[1] = d1; pp[2] = d2; pp[3] = d3; pp[4] = sq;
        }
        __syncthreads();
        if (kh == 0) {
            const float* pp = prt + lr * 5;
            d0 += pp[0]; d1 += pp[1]; d2 += pp[2]; d3 += pp[3]; sq += pp[4];
            float invnj = 1.0f / sqrtf(sq);
            int gj = tt * TILE + lr;
            float c0 = d0 * s_invna[0] * invnj;
            float c1 = d1 * s_invna[1] * invnj;
            float c2 = d2 * s_invna[2] * invnj;
            float c3 = d3 * s_invna[3] * invnj;
            sdm[0 * Nd + gj] = sqrtf(fmaxf(2.f - 2.f * c0, 0.f));
            sdm[1 * Nd + gj] = sqrtf(fmaxf(2.f - 2.f * c1, 0.f));
            sdm[2 * Nd + gj] = sqrtf(fmaxf(2.f - 2.f * c2, 0.f));
            sdm[3 * Nd + gj] = sqrtf(fmaxf(2.f - 2.f * c3, 0.f));
        }
        __syncthreads();   // tile buffer reused next iteration
    }

    // ---- triplet reduction: thread t = candidate negative n ----
    float        lsum = 0.0f;
    unsigned int lcnt = 0;

#pragma unroll
    for (int i = 0; i < ANCH; i++) {
        int a  = blk * ANCH + i;
        int la = slab[a];

        if (t == 0) snpos = 0;
        __syncthreads();
        if (slab[t] == la && t != a) {
            int k = atomicAdd(&snpos, 1);
            spos[k] = t;
        }
        __syncthreads();
        int P = snpos;
        if (t < P) spp[t] = sdm[i * Nd + spos[t]];   // pre-gather positive distances
        __syncthreads();

        if (slab[t] != la) {
            float dan = sdm[i * Nd + t];
#pragma unroll 4
            for (int q = 0; q < P; q++) {
                float diff = spp[q] - dan;   // margin = 0
                if (diff > 0.0f) { lsum += diff; lcnt++; }
            }
        }
        __syncthreads();   // spos/spp reused next anchor
    }

    // ---- block reduce (sum, count) ----
#pragma unroll
    for (int o = 16; o > 0; o >>= 1) {
        lsum += __shfl_xor_sync(0xffffffffu, lsum, o);
        lcnt += __shfl_xor_sync(0xffffffffu, lcnt, o);
    }
    if (lane == 0) { swsum[w] = lsum; swcnt[w] = lcnt; }
    __syncthreads();

    if (t == 0) {
        float bs = 0.0f; unsigned int bc = 0;
#pragma unroll
        for (int k = 0; k < 16; k++) { bs += swsum[k]; bc += swcnt[k]; }
        g_part[blk] = bs;
        g_cntp[blk] = bc;
        __threadfence();
        unsigned int old = atomicAdd(&g_done, 1);
        sIsLast = (old == GRID - 1);
    }
    __syncthreads();

    // ---- last block finalizes (AvgNonZeroReducer) ----
    if (sIsLast) {
        __threadfence();
        float        s = 0.0f;
        unsigned int c = 0;
        if (t < GRID) {
            s = ((volatile float*)g_part)[t];
            c = ((volatile unsigned int*)g_cntp)[t];
        }
#pragma unroll
        for (int o = 16; o > 0; o >>= 1) {
            s += __shfl_xor_sync(0xffffffffu, s, o);
            c += __shfl_xor_sync(0xffffffffu, c, o);
        }
        if (t < GRID && lane == 0) { swsum[w] = s; swcnt[w] = c; }
        __syncthreads();
        if (t == 0) {
            float S = swsum[0] + swsum[1] + swsum[2] + swsum[3];
            unsigned int C = swcnt[0] + swcnt[1] + swcnt[2] + swcnt[3];
            out[0] = (C > 0) ? (S / (float)C) : 0.0f;
            g_done = 0;   // reset for next graph replay
        }
    }
}

extern "C" void kernel_launch(void* const* d_in, const int* in_sizes, int n_in,
                              void* d_out, int out_size) {
    const float* feat   = (const float*)d_in[0];   // [128, 4, 128] float32
    const int*   labels = (const int*)d_in[1];     // [128] int32
    float*       out    = (float*)d_out;           // scalar float32

    cudaFuncSetAttribute(fused_triplet_kernel,
                         cudaFuncAttributeMaxDynamicSharedMemorySize,
                         DYN_SMEM_BYTES);
    fused_triplet_kernel<<<GRID, NT, DYN_SMEM_BYTES>>>(feat, labels, out);
}